// round 12
// baseline (speedup 1.0000x reference)
#include <cuda_runtime.h>
#include <cuda_bf16.h>
#include <math_constants.h>
#include <cstdint>

// Problem constants
#define BB 4
#define SS 4096
#define EE 256
#define DD 32

typedef unsigned long long ull;

// ---- packed f32x2 helpers (proj kernel) ----
__device__ __forceinline__ ull ffma2(ull a, ull b, ull c) {
    ull d; asm("fma.rn.f32x2 %0, %1, %2, %3;" : "=l"(d) : "l"(a), "l"(b), "l"(c)); return d;
}
__device__ __forceinline__ ull pack2(float x, float y) {
    ull r; asm("mov.b64 %0, {%1, %2};" : "=l"(r) : "f"(x), "f"(y)); return r;
}
__device__ __forceinline__ float2 unpack2(ull u) {
    float2 v; asm("mov.b64 {%0, %1}, %2;" : "=f"(v.x), "=f"(v.y) : "l"(u)); return v;
}

// ---- bf16 mma.sync m16n8k16 (arch-generic PTX -> HMMA on sm_103) ----
__device__ __forceinline__ void mma_bf16(float c[4], const uint32_t a[4],
                                         uint32_t b0, uint32_t b1) {
    asm volatile(
        "mma.sync.aligned.m16n8k16.row.col.f32.bf16.bf16.f32 "
        "{%0,%1,%2,%3}, {%4,%5,%6,%7}, {%8,%9}, {%0,%1,%2,%3};"
        : "+f"(c[0]), "+f"(c[1]), "+f"(c[2]), "+f"(c[3])
        : "r"(a[0]), "r"(a[1]), "r"(a[2]), "r"(a[3]), "r"(b0), "r"(b1));
}
__device__ __forceinline__ uint32_t cvt_bf2(float a, float b) {
    uint32_t r;
    asm("cvt.rn.satfinite.bf16x2.f32 %0, %1, %2;" : "=r"(r) : "f"(b), "f"(a));
    return r;
}
__device__ __forceinline__ float ex2f(float x) {
    float y; asm("ex2.approx.f32 %0, %1;" : "=f"(y) : "f"(x)); return y;
}

// Device scratch.
// Q (pre-scaled by log2e) / K: hi-lo bf16 splits, [B*S][32] row-major.
// V: PAIRED words: word (s/2)*32+d = {V[s_even][d] lo16, V[s_odd][d] hi16}.
__device__ __nv_bfloat16 g_qh[BB * SS * DD], g_ql[BB * SS * DD];
__device__ __nv_bfloat16 g_kh[BB * SS * DD], g_kl[BB * SS * DD];
__device__ uint32_t g_vph[BB * SS * DD / 2], g_vpl[BB * SS * DD / 2];

// ---------------------------------------------------------------------------
// Projection: q/k/v = x @ W (fp32 FFMA2); q scaled by log2e; bf16 hi/lo splits.
// ---------------------------------------------------------------------------
__global__ __launch_bounds__(256, 1) void proj_kernel(
    const float* __restrict__ x,
    const float* __restrict__ Wq,
    const float* __restrict__ Wk,
    const float* __restrict__ Wv)
{
    __shared__ float xs[32 * EE];
    const int row0 = blockIdx.x * 32;
    const int tid = threadIdx.x;

    const float4* xg = (const float4*)(x + (size_t)row0 * EE);
    float4* xs4 = (float4*)xs;
#pragma unroll
    for (int i = 0; i < 8; i++) xs4[tid + i * 256] = xg[tid + i * 256];
    __syncthreads();

    const int col = tid & 31;
    const int rg  = tid >> 5;

    ull aq2[4], ak2[4], av2[4];
#pragma unroll
    for (int rr = 0; rr < 4; rr++) { aq2[rr] = 0; ak2[rr] = 0; av2[rr] = 0; }

#pragma unroll 2
    for (int e = 0; e < EE; e += 2) {
        const ull wq2 = pack2(__ldg(&Wq[e * DD + col]), __ldg(&Wq[(e + 1) * DD + col]));
        const ull wk2 = pack2(__ldg(&Wk[e * DD + col]), __ldg(&Wk[(e + 1) * DD + col]));
        const ull wv2 = pack2(__ldg(&Wv[e * DD + col]), __ldg(&Wv[(e + 1) * DD + col]));
#pragma unroll
        for (int rr = 0; rr < 4; rr++) {
            const ull xv2 = *(const ull*)&xs[(rg * 4 + rr) * EE + e];
            aq2[rr] = ffma2(xv2, wq2, aq2[rr]);
            ak2[rr] = ffma2(xv2, wk2, ak2[rr]);
            av2[rr] = ffma2(xv2, wv2, av2[rr]);
        }
    }

#pragma unroll
    for (int rr = 0; rr < 4; rr++) {
        const int r = row0 + rg * 4 + rr;
        const float2 q2 = unpack2(aq2[rr]);
        const float2 k2 = unpack2(ak2[rr]);
        const float2 v2 = unpack2(av2[rr]);
        const float q = (q2.x + q2.y) * 1.4426950408889634f;   // fold log2(e)
        const float k = k2.x + k2.y, v = v2.x + v2.y;
        const int o = r * DD + col;

        const __nv_bfloat16 qh = __float2bfloat16(q);
        g_qh[o] = qh; g_ql[o] = __float2bfloat16(q - __bfloat162float(qh));
        const __nv_bfloat16 kh = __float2bfloat16(k);
        g_kh[o] = kh; g_kl[o] = __float2bfloat16(k - __bfloat162float(kh));

        const __nv_bfloat16 vh = __float2bfloat16(v);
        const __nv_bfloat16 vl = __float2bfloat16(v - __bfloat162float(vh));
        const int wp = (r >> 1) * DD + col;       // paired-word index
        ((__nv_bfloat16*)g_vph)[wp * 2 + (r & 1)] = vh;
        ((__nv_bfloat16*)g_vpl)[wp * 2 + (r & 1)] = vl;
    }
}

// ---------------------------------------------------------------------------
// HMMA flash attention. CTA = 128 threads = 4 warps; BQ=64 (16 q/warp),
// BK=64 keys/chunk, 64 chunks. Grid = 64*4 = 256 CTAs -> 2 CTAs/SM resident;
// independent CTAs interleave phases on each SMSP (softmax of one covered by
// mma issue of the other). Split-bf16 (hi+lo), 3 mmas/product, no max-shift,
// bare ex2 softmax (log2e folded into Q). P stays in registers.
//
// SMEM words (uint32 = bf16x2):
//   Q : [0,2048)      hi @0, lo @1024; row r -> r*16 + d2
//   K : [2048,7168)   2 buffers d*2560: hi 64rows x 20-stride, lo +1280
//   V : [7168,12288)  2 buffers d*2560: hi 32k2 x 40-stride (paired), lo +1280
// ---------------------------------------------------------------------------
#define QPH_W 0
#define QPL_W 1024
#define KBASE_W 2048
#define VBASE_W 7168
#define SMEM_BYTES (12288 * 4)

__global__ __launch_bounds__(128, 2) void attn_mma(float* __restrict__ out)
{
    extern __shared__ uint32_t smw[];
    const int tid  = threadIdx.x;
    const int wid  = tid >> 5, lane = tid & 31;
    const int gid  = lane >> 2, tig = lane & 3;
    const int b    = blockIdx.y;
    const int q0   = blockIdx.x * 64;
    const int qbase = wid * 16;

    const __nv_bfloat16* khb = g_kh + (size_t)b * SS * DD;
    const __nv_bfloat16* klb = g_kl + (size_t)b * SS * DD;
    const uint32_t* vphb = g_vph + (size_t)b * (SS / 2) * DD;
    const uint32_t* vplb = g_vpl + (size_t)b * (SS / 2) * DD;

    // ---- one-time Q tile load: 64 rows x {hi,lo} = 512 uint4 ----
#pragma unroll
    for (int it = 0; it < 4; it++) {
        const int u = tid + it * 128;
        const int split = u >> 8, r = (u >> 2) & 63, c4 = u & 3;
        const __nv_bfloat16* src = split ? g_ql : g_qh;
        const uint4 d = *(const uint4*)(src + (size_t)(b * SS + q0 + r) * DD + c4 * 8);
        *(uint4*)&smw[(split ? QPL_W : QPH_W) + r * 16 + c4 * 4] = d;
    }

    // ---- per-thread staged-load coordinates ----
    int k_off[4], k_drel[4];
    const __nv_bfloat16* k_src[4];
    int v_goff[4], v_drel[4];
    const uint32_t* v_src[4];
#pragma unroll
    for (int it = 0; it < 4; it++) {
        const int u = tid + it * 128;
        {   // K: split | row(64) | c4(4 uint4)
            const int split = u >> 8, r = (u >> 2) & 63, c4 = u & 3;
            k_src[it]  = split ? klb : khb;
            k_off[it]  = r * DD + c4 * 8;
            k_drel[it] = (split ? 1280 : 0) + r * 20 + c4 * 4;
        }
        {   // V: split | k2(32) | nb(8 uint4 of words)
            const int split = u >> 8, k2 = (u >> 3) & 31, nb = u & 7;
            v_src[it]  = split ? vplb : vphb;
            v_goff[it] = k2 * DD + nb * 4;       // words within chunk
            v_drel[it] = (split ? 1280 : 0) + k2 * 40 + nb * 4;
        }
    }

    // ---- prologue: load chunk 0 into buffer 0 ----
    uint4 kreg[4], vreg[4];
#pragma unroll
    for (int it = 0; it < 4; it++) {
        kreg[it] = *(const uint4*)(k_src[it] + k_off[it]);
        vreg[it] = *(const uint4*)(v_src[it] + v_goff[it]);
    }
#pragma unroll
    for (int it = 0; it < 4; it++) {
        *(uint4*)&smw[KBASE_W + k_drel[it]] = kreg[it];
        *(uint4*)&smw[VBASE_W + v_drel[it]] = vreg[it];
    }
    __syncthreads();

    // ---- Q fragments (persist): [split][kt][4] ----
    uint32_t qf[2][2][4];
#pragma unroll
    for (int s = 0; s < 2; s++)
#pragma unroll
        for (int kt = 0; kt < 2; kt++) {
            const int base = s ? QPL_W : QPH_W;
            qf[s][kt][0] = smw[base + (qbase + gid) * 16 + kt * 8 + tig];
            qf[s][kt][1] = smw[base + (qbase + gid + 8) * 16 + kt * 8 + tig];
            qf[s][kt][2] = smw[base + (qbase + gid) * 16 + kt * 8 + tig + 4];
            qf[s][kt][3] = smw[base + (qbase + gid + 8) * 16 + kt * 8 + tig + 4];
        }

    float acc[4][4];
#pragma unroll
    for (int i = 0; i < 4; i++)
#pragma unroll
        for (int j = 0; j < 4; j++) acc[i][j] = 0.f;
    float l0 = 0.f, l8 = 0.f;

    for (int nc = 0; nc < SS / 64; nc++) {
        const int db = nc & 1;
        const bool pre = (nc + 1 < SS / 64);

        // stage next chunk (LDG latency hidden under QK mmas)
        if (pre) {
            const int kcK = (nc + 1) * 64 * DD;        // bf16 elements
            const int kcV = (nc + 1) * 32 * DD;        // paired words
#pragma unroll
            for (int it = 0; it < 4; it++) {
                kreg[it] = *(const uint4*)(k_src[it] + kcK + k_off[it]);
                vreg[it] = *(const uint4*)(v_src[it] + kcV + v_goff[it]);
            }
        }

        // ---- QK: S(16q x 64k) ----
        float c[8][4];
#pragma unroll
        for (int nt = 0; nt < 8; nt++)
#pragma unroll
            for (int j = 0; j < 4; j++) c[nt][j] = 0.f;

        const int kbh = KBASE_W + db * 2560, kbl = kbh + 1280;
#pragma unroll
        for (int kt = 0; kt < 2; kt++)
#pragma unroll
            for (int nt = 0; nt < 8; nt++) {
                const int w0 = (nt * 8 + gid) * 20 + kt * 8 + tig;
                const uint32_t kh0 = smw[kbh + w0], kh1 = smw[kbh + w0 + 4];
                const uint32_t kl0 = smw[kbl + w0], kl1 = smw[kbl + w0 + 4];
                mma_bf16(c[nt], qf[0][kt], kh0, kh1);
                mma_bf16(c[nt], qf[0][kt], kl0, kl1);
                mma_bf16(c[nt], qf[1][kt], kh0, kh1);
            }

        // commit staged chunk to the other buffer
        if (pre) {
            const int o2 = (db ^ 1) * 2560;
#pragma unroll
            for (int it = 0; it < 4; it++) {
                *(uint4*)&smw[KBASE_W + o2 + k_drel[it]] = kreg[it];
                *(uint4*)&smw[VBASE_W + o2 + v_drel[it]] = vreg[it];
            }
        }

        // ---- softmax: p = ex2(s) (log2e pre-folded), repack to A-frags ----
        uint32_t aph[4][4], apl[4][4];
#pragma unroll
        for (int nt = 0; nt < 8; nt++) {
            const float p0 = ex2f(c[nt][0]);
            const float p1 = ex2f(c[nt][1]);
            const float p2 = ex2f(c[nt][2]);
            const float p3 = ex2f(c[nt][3]);
            l0 += p0 + p1;
            l8 += p2 + p3;
            const uint32_t h01 = cvt_bf2(p0, p1);
            const uint32_t h23 = cvt_bf2(p2, p3);
            const float r0 = p0 - __uint_as_float(h01 << 16);
            const float r1 = p1 - __uint_as_float(h01 & 0xFFFF0000u);
            const float r2 = p2 - __uint_as_float(h23 << 16);
            const float r3 = p3 - __uint_as_float(h23 & 0xFFFF0000u);
            const uint32_t q01 = cvt_bf2(r0, r1);
            const uint32_t q23 = cvt_bf2(r2, r3);
            const int kt2 = nt >> 1, hi = (nt & 1) * 2;
            aph[kt2][hi]     = h01; aph[kt2][hi + 1] = h23;
            apl[kt2][hi]     = q01; apl[kt2][hi + 1] = q23;
        }

        // ---- PV: O(16q x 32d) ----
        const int vbh = VBASE_W + db * 2560, vbl = vbh + 1280;
#pragma unroll
        for (int kt2 = 0; kt2 < 4; kt2++)
#pragma unroll
            for (int nt2 = 0; nt2 < 4; nt2++) {
                const int w0 = (kt2 * 8 + tig) * 40 + nt2 * 8 + gid;
                const uint32_t vh0 = smw[vbh + w0], vh1 = smw[vbh + w0 + 160];
                const uint32_t vl0 = smw[vbl + w0], vl1 = smw[vbl + w0 + 160];
                mma_bf16(acc[nt2], aph[kt2], vh0, vh1);
                mma_bf16(acc[nt2], aph[kt2], vl0, vl1);
                mma_bf16(acc[nt2], apl[kt2], vh0, vh1);
            }

        __syncthreads();
    }

    // ---- epilogue: reduce l over the 4 tig lanes; write out ----
    l0 += __shfl_xor_sync(0xffffffffu, l0, 1, 4);
    l0 += __shfl_xor_sync(0xffffffffu, l0, 2, 4);
    l8 += __shfl_xor_sync(0xffffffffu, l8, 1, 4);
    l8 += __shfl_xor_sync(0xffffffffu, l8, 2, 4);
    const float scaling = 0.17677669529663687f;  // 32^-0.5 (post-softmax, per reference)
    const float inv0 = scaling / l0;
    const float inv8 = scaling / l8;

    const size_t qg0 = (size_t)b * SS + q0 + qbase + gid;
#pragma unroll
    for (int nt2 = 0; nt2 < 4; nt2++) {
        float2 o0, o8;
        o0.x = acc[nt2][0] * inv0; o0.y = acc[nt2][1] * inv0;
        o8.x = acc[nt2][2] * inv8; o8.y = acc[nt2][3] * inv8;
        *(float2*)(out + qg0 * DD + nt2 * 8 + tig * 2) = o0;
        *(float2*)(out + (qg0 + 8) * DD + nt2 * 8 + tig * 2) = o8;
    }
}

// ---------------------------------------------------------------------------
extern "C" void kernel_launch(void* const* d_in, const int* in_sizes, int n_in,
                              void* d_out, int out_size)
{
    const float* x  = (const float*)d_in[0];
    const float* Wq = (const float*)d_in[1];
    const float* Wk = (const float*)d_in[2];
    const float* Wv = (const float*)d_in[3];
    float* out = (float*)d_out;

    proj_kernel<<<(BB * SS) / 32, 256>>>(x, Wq, Wk, Wv);

    cudaFuncSetAttribute(attn_mma, cudaFuncAttributeMaxDynamicSharedMemorySize, SMEM_BYTES);
    dim3 grid(SS / 64, BB);
    attn_mma<<<grid, 128, SMEM_BYTES>>>(out);
}

// round 13
// speedup vs baseline: 1.5000x; 1.5000x over previous
#include <cuda_runtime.h>
#include <cuda_bf16.h>
#include <math_constants.h>
#include <cstdint>

// Problem constants
#define BB 4
#define SS 4096
#define EE 256
#define DD 32

typedef unsigned long long ull;

// ---- packed f32x2 helpers (proj kernel) ----
__device__ __forceinline__ ull ffma2(ull a, ull b, ull c) {
    ull d; asm("fma.rn.f32x2 %0, %1, %2, %3;" : "=l"(d) : "l"(a), "l"(b), "l"(c)); return d;
}
__device__ __forceinline__ ull pack2(float x, float y) {
    ull r; asm("mov.b64 %0, {%1, %2};" : "=l"(r) : "f"(x), "f"(y)); return r;
}
__device__ __forceinline__ float2 unpack2(ull u) {
    float2 v; asm("mov.b64 {%0, %1}, %2;" : "=f"(v.x), "=f"(v.y) : "l"(u)); return v;
}

// ---- bf16 mma.sync m16n8k16 (arch-generic PTX -> HMMA on sm_103) ----
__device__ __forceinline__ void mma_bf16(float c[4], const uint32_t a[4],
                                         uint32_t b0, uint32_t b1) {
    asm volatile(
        "mma.sync.aligned.m16n8k16.row.col.f32.bf16.bf16.f32 "
        "{%0,%1,%2,%3}, {%4,%5,%6,%7}, {%8,%9}, {%0,%1,%2,%3};"
        : "+f"(c[0]), "+f"(c[1]), "+f"(c[2]), "+f"(c[3])
        : "r"(a[0]), "r"(a[1]), "r"(a[2]), "r"(a[3]), "r"(b0), "r"(b1));
}
__device__ __forceinline__ uint32_t cvt_bf2(float a, float b) {
    uint32_t r;
    asm("cvt.rn.satfinite.bf16x2.f32 %0, %1, %2;" : "=r"(r) : "f"(b), "f"(a));
    return r;
}
__device__ __forceinline__ float ex2f(float x) {
    float y; asm("ex2.approx.f32 %0, %1;" : "=f"(y) : "f"(x)); return y;
}

// Device scratch.
// Q (pre-scaled by log2e) / K: hi-lo bf16 splits, [B*S][32] row-major.
// V: PAIRED words: word (s/2)*32+d = {V[s_even][d] lo16, V[s_odd][d] hi16}.
__device__ __nv_bfloat16 g_qh[BB * SS * DD], g_ql[BB * SS * DD];
__device__ __nv_bfloat16 g_kh[BB * SS * DD], g_kl[BB * SS * DD];
__device__ uint32_t g_vph[BB * SS * DD / 2], g_vpl[BB * SS * DD / 2];
// Split-K partials: [half][B*S*D] acc, [half][B*S] denominators.
__device__ float g_pacc[2][BB * SS * DD];
__device__ float g_pl[2][BB * SS];

// ---------------------------------------------------------------------------
// Projection: q/k/v = x @ W (fp32 FFMA2); q scaled by log2e; bf16 hi/lo splits.
// ---------------------------------------------------------------------------
__global__ __launch_bounds__(256, 1) void proj_kernel(
    const float* __restrict__ x,
    const float* __restrict__ Wq,
    const float* __restrict__ Wk,
    const float* __restrict__ Wv)
{
    __shared__ float xs[32 * EE];
    const int row0 = blockIdx.x * 32;
    const int tid = threadIdx.x;

    const float4* xg = (const float4*)(x + (size_t)row0 * EE);
    float4* xs4 = (float4*)xs;
#pragma unroll
    for (int i = 0; i < 8; i++) xs4[tid + i * 256] = xg[tid + i * 256];
    __syncthreads();

    const int col = tid & 31;
    const int rg  = tid >> 5;

    ull aq2[4], ak2[4], av2[4];
#pragma unroll
    for (int rr = 0; rr < 4; rr++) { aq2[rr] = 0; ak2[rr] = 0; av2[rr] = 0; }

#pragma unroll 2
    for (int e = 0; e < EE; e += 2) {
        const ull wq2 = pack2(__ldg(&Wq[e * DD + col]), __ldg(&Wq[(e + 1) * DD + col]));
        const ull wk2 = pack2(__ldg(&Wk[e * DD + col]), __ldg(&Wk[(e + 1) * DD + col]));
        const ull wv2 = pack2(__ldg(&Wv[e * DD + col]), __ldg(&Wv[(e + 1) * DD + col]));
#pragma unroll
        for (int rr = 0; rr < 4; rr++) {
            const ull xv2 = *(const ull*)&xs[(rg * 4 + rr) * EE + e];
            aq2[rr] = ffma2(xv2, wq2, aq2[rr]);
            ak2[rr] = ffma2(xv2, wk2, ak2[rr]);
            av2[rr] = ffma2(xv2, wv2, av2[rr]);
        }
    }

#pragma unroll
    for (int rr = 0; rr < 4; rr++) {
        const int r = row0 + rg * 4 + rr;
        const float2 q2 = unpack2(aq2[rr]);
        const float2 k2 = unpack2(ak2[rr]);
        const float2 v2 = unpack2(av2[rr]);
        const float q = (q2.x + q2.y) * 1.4426950408889634f;   // fold log2(e)
        const float k = k2.x + k2.y, v = v2.x + v2.y;
        const int o = r * DD + col;

        const __nv_bfloat16 qh = __float2bfloat16(q);
        g_qh[o] = qh; g_ql[o] = __float2bfloat16(q - __bfloat162float(qh));
        const __nv_bfloat16 kh = __float2bfloat16(k);
        g_kh[o] = kh; g_kl[o] = __float2bfloat16(k - __bfloat162float(kh));

        const __nv_bfloat16 vh = __float2bfloat16(v);
        const __nv_bfloat16 vl = __float2bfloat16(v - __bfloat162float(vh));
        const int wp = (r >> 1) * DD + col;       // paired-word index
        ((__nv_bfloat16*)g_vph)[wp * 2 + (r & 1)] = vh;
        ((__nv_bfloat16*)g_vpl)[wp * 2 + (r & 1)] = vl;
    }
}

// ---------------------------------------------------------------------------
// HMMA flash attention, split-K. CTA = 256 threads = 8 warps, BQ=128
// (16 q/warp, the proven R10 reuse shape); each CTA handles HALF the keys
// (32 chunks of 64). Grid 32 x 4 x 2 = 256 CTAs -> 2 resident CTAs/SM:
// independent CTAs interleave phases (one's softmax covered by the other's
// mma issue). No max-shift -> split-K merge is purely additive; partial
// acc/l written raw, combined by merge_kernel.
// Split-bf16 (hi+lo), 3 mmas/product; bare ex2 (log2e folded into Q);
// paired-V words (no repack ALU in the hot loop).
//
// SMEM words (uint32 = bf16x2):
//   Q : [0,4096)       hi @0, lo @2048; row r -> r*16 + d2
//   K : [4096,9216)    2 buffers d*2560: hi 64rows x 20-stride, lo +1280
//   V : [9216,14336)   2 buffers d*2560: hi 32k2 x 40-stride (paired), lo +1280
// ---------------------------------------------------------------------------
#define QPH_W 0
#define QPL_W 2048
#define KBASE_W 4096
#define VBASE_W 9216
#define SMEM_BYTES (14336 * 4)

__global__ __launch_bounds__(256, 2) void attn_mma()
{
    extern __shared__ uint32_t smw[];
    const int tid  = threadIdx.x;
    const int wid  = tid >> 5, lane = tid & 31;
    const int gid  = lane >> 2, tig = lane & 3;
    const int b    = blockIdx.y;
    const int q0   = blockIdx.x * 128;
    const int half = blockIdx.z;
    const int qbase = wid * 16;

    const __nv_bfloat16* khb = g_kh + (size_t)b * SS * DD;
    const __nv_bfloat16* klb = g_kl + (size_t)b * SS * DD;
    const uint32_t* vphb = g_vph + (size_t)b * (SS / 2) * DD;
    const uint32_t* vplb = g_vpl + (size_t)b * (SS / 2) * DD;

    // ---- one-time Q tile load: 128 rows x {hi,lo} = 1024 uint4 ----
#pragma unroll
    for (int it = 0; it < 4; it++) {
        const int u = tid + it * 256;
        const int split = u >> 9, r = (u >> 2) & 127, c4 = u & 3;
        const __nv_bfloat16* src = split ? g_ql : g_qh;
        const uint4 d = *(const uint4*)(src + (size_t)(b * SS + q0 + r) * DD + c4 * 8);
        *(uint4*)&smw[(split ? QPL_W : QPH_W) + r * 16 + c4 * 4] = d;
    }

    // ---- per-thread staged-load coordinates (2 units each for K and V) ----
    int k_off[2], k_drel[2];
    const __nv_bfloat16* k_src[2];
    int v_goff[2], v_drel[2];
    const uint32_t* v_src[2];
#pragma unroll
    for (int it = 0; it < 2; it++) {
        const int u = tid + it * 256;
        {   // K: split | row(64) | c4(4 uint4)
            const int split = u >> 8, r = (u >> 2) & 63, c4 = u & 3;
            k_src[it]  = split ? klb : khb;
            k_off[it]  = r * DD + c4 * 8;
            k_drel[it] = (split ? 1280 : 0) + r * 20 + c4 * 4;
        }
        {   // V: split | k2(32) | nb(8 uint4 of paired words)
            const int split = u >> 8, k2 = (u >> 3) & 31, nb = u & 7;
            v_src[it]  = split ? vplb : vphb;
            v_goff[it] = k2 * DD + nb * 4;       // words within chunk
            v_drel[it] = (split ? 1280 : 0) + k2 * 40 + nb * 4;
        }
    }

    // ---- prologue: load first chunk of this half into buffer 0 ----
    const int c0K = half * 32 * 64 * DD;     // bf16 elements
    const int c0V = half * 32 * 32 * DD;     // paired words
    uint4 kreg[2], vreg[2];
#pragma unroll
    for (int it = 0; it < 2; it++) {
        kreg[it] = *(const uint4*)(k_src[it] + c0K + k_off[it]);
        vreg[it] = *(const uint4*)(v_src[it] + c0V + v_goff[it]);
    }
#pragma unroll
    for (int it = 0; it < 2; it++) {
        *(uint4*)&smw[KBASE_W + k_drel[it]] = kreg[it];
        *(uint4*)&smw[VBASE_W + v_drel[it]] = vreg[it];
    }
    __syncthreads();

    // ---- Q fragments (persist): [split][kt][4] ----
    uint32_t qf[2][2][4];
#pragma unroll
    for (int s = 0; s < 2; s++)
#pragma unroll
        for (int kt = 0; kt < 2; kt++) {
            const int base = s ? QPL_W : QPH_W;
            qf[s][kt][0] = smw[base + (qbase + gid) * 16 + kt * 8 + tig];
            qf[s][kt][1] = smw[base + (qbase + gid + 8) * 16 + kt * 8 + tig];
            qf[s][kt][2] = smw[base + (qbase + gid) * 16 + kt * 8 + tig + 4];
            qf[s][kt][3] = smw[base + (qbase + gid + 8) * 16 + kt * 8 + tig + 4];
        }

    float acc[4][4];
#pragma unroll
    for (int i = 0; i < 4; i++)
#pragma unroll
        for (int j = 0; j < 4; j++) acc[i][j] = 0.f;
    float l0 = 0.f, l8 = 0.f;

    for (int nc = 0; nc < 32; nc++) {
        const int db = nc & 1;
        const bool pre = (nc + 1 < 32);

        // stage next chunk (LDG latency hidden under QK mmas)
        if (pre) {
            const int kcK = c0K + (nc + 1) * 64 * DD;
            const int kcV = c0V + (nc + 1) * 32 * DD;
#pragma unroll
            for (int it = 0; it < 2; it++) {
                kreg[it] = *(const uint4*)(k_src[it] + kcK + k_off[it]);
                vreg[it] = *(const uint4*)(v_src[it] + kcV + v_goff[it]);
            }
        }

        // ---- QK: S(16q x 64k) ----
        float c[8][4];
#pragma unroll
        for (int nt = 0; nt < 8; nt++)
#pragma unroll
            for (int j = 0; j < 4; j++) c[nt][j] = 0.f;

        const int kbh = KBASE_W + db * 2560, kbl = kbh + 1280;
#pragma unroll
        for (int kt = 0; kt < 2; kt++)
#pragma unroll
            for (int nt = 0; nt < 8; nt++) {
                const int w0 = (nt * 8 + gid) * 20 + kt * 8 + tig;
                const uint32_t kh0 = smw[kbh + w0], kh1 = smw[kbh + w0 + 4];
                const uint32_t kl0 = smw[kbl + w0], kl1 = smw[kbl + w0 + 4];
                mma_bf16(c[nt], qf[0][kt], kh0, kh1);
                mma_bf16(c[nt], qf[0][kt], kl0, kl1);
                mma_bf16(c[nt], qf[1][kt], kh0, kh1);
            }

        // commit staged chunk to the other buffer
        if (pre) {
            const int o2 = (db ^ 1) * 2560;
#pragma unroll
            for (int it = 0; it < 2; it++) {
                *(uint4*)&smw[KBASE_W + o2 + k_drel[it]] = kreg[it];
                *(uint4*)&smw[VBASE_W + o2 + v_drel[it]] = vreg[it];
            }
        }

        // ---- softmax: p = ex2(s) (log2e pre-folded), repack to A-frags ----
        uint32_t aph[4][4], apl[4][4];
#pragma unroll
        for (int nt = 0; nt < 8; nt++) {
            const float p0 = ex2f(c[nt][0]);
            const float p1 = ex2f(c[nt][1]);
            const float p2 = ex2f(c[nt][2]);
            const float p3 = ex2f(c[nt][3]);
            l0 += p0 + p1;
            l8 += p2 + p3;
            const uint32_t h01 = cvt_bf2(p0, p1);
            const uint32_t h23 = cvt_bf2(p2, p3);
            const float r0 = p0 - __uint_as_float(h01 << 16);
            const float r1 = p1 - __uint_as_float(h01 & 0xFFFF0000u);
            const float r2 = p2 - __uint_as_float(h23 << 16);
            const float r3 = p3 - __uint_as_float(h23 & 0xFFFF0000u);
            const uint32_t q01 = cvt_bf2(r0, r1);
            const uint32_t q23 = cvt_bf2(r2, r3);
            const int kt2 = nt >> 1, hi = (nt & 1) * 2;
            aph[kt2][hi]     = h01; aph[kt2][hi + 1] = h23;
            apl[kt2][hi]     = q01; apl[kt2][hi + 1] = q23;
        }

        // ---- PV: O(16q x 32d) ----
        const int vbh = VBASE_W + db * 2560, vbl = vbh + 1280;
#pragma unroll
        for (int kt2 = 0; kt2 < 4; kt2++)
#pragma unroll
            for (int nt2 = 0; nt2 < 4; nt2++) {
                const int w0 = (kt2 * 8 + tig) * 40 + nt2 * 8 + gid;
                const uint32_t vh0 = smw[vbh + w0], vh1 = smw[vbh + w0 + 160];
                const uint32_t vl0 = smw[vbl + w0], vl1 = smw[vbl + w0 + 160];
                mma_bf16(acc[nt2], aph[kt2], vh0, vh1);
                mma_bf16(acc[nt2], aph[kt2], vl0, vl1);
                mma_bf16(acc[nt2], apl[kt2], vh0, vh1);
            }

        __syncthreads();
    }

    // ---- epilogue: reduce l over the 4 tig lanes; write RAW partials ----
    l0 += __shfl_xor_sync(0xffffffffu, l0, 1, 4);
    l0 += __shfl_xor_sync(0xffffffffu, l0, 2, 4);
    l8 += __shfl_xor_sync(0xffffffffu, l8, 1, 4);
    l8 += __shfl_xor_sync(0xffffffffu, l8, 2, 4);

    const size_t row0 = (size_t)b * SS + q0 + qbase + gid;
    float* pa = g_pacc[half];
    if (tig == 0) {
        g_pl[half][row0]     = l0;
        g_pl[half][row0 + 8] = l8;
    }
#pragma unroll
    for (int nt2 = 0; nt2 < 4; nt2++) {
        *(float2*)(pa + row0 * DD + nt2 * 8 + tig * 2) =
            make_float2(acc[nt2][0], acc[nt2][1]);
        *(float2*)(pa + (row0 + 8) * DD + nt2 * 8 + tig * 2) =
            make_float2(acc[nt2][2], acc[nt2][3]);
    }
}

// ---------------------------------------------------------------------------
// Merge: out = (acc0 + acc1) * scaling / (l0 + l1).
// ---------------------------------------------------------------------------
__global__ __launch_bounds__(256, 1) void merge_kernel(float* __restrict__ out)
{
    const int i4 = blockIdx.x * 256 + threadIdx.x;   // float4 index
    const int row = i4 >> 3;                          // DD/4 = 8 float4 per row
    const float l = g_pl[0][row] + g_pl[1][row];
    const float s = 0.17677669529663687f / l;         // 32^-0.5 post-softmax
    const float4 a = ((const float4*)g_pacc[0])[i4];
    const float4 b = ((const float4*)g_pacc[1])[i4];
    float4 o;
    o.x = (a.x + b.x) * s; o.y = (a.y + b.y) * s;
    o.z = (a.z + b.z) * s; o.w = (a.w + b.w) * s;
    ((float4*)out)[i4] = o;
}

// ---------------------------------------------------------------------------
extern "C" void kernel_launch(void* const* d_in, const int* in_sizes, int n_in,
                              void* d_out, int out_size)
{
    const float* x  = (const float*)d_in[0];
    const float* Wq = (const float*)d_in[1];
    const float* Wk = (const float*)d_in[2];
    const float* Wv = (const float*)d_in[3];
    float* out = (float*)d_out;

    proj_kernel<<<(BB * SS) / 32, 256>>>(x, Wq, Wk, Wv);

    cudaFuncSetAttribute(attn_mma, cudaFuncAttributeMaxDynamicSharedMemorySize, SMEM_BYTES);
    dim3 grid(SS / 128, BB, 2);
    attn_mma<<<grid, 256, SMEM_BYTES>>>();

    merge_kernel<<<(BB * SS * DD / 4) / 256, 256>>>(out);
}

// round 14
// speedup vs baseline: 1.5555x; 1.0370x over previous
#include <cuda_runtime.h>
#include <cuda_bf16.h>
#include <math_constants.h>
#include <cstdint>

// Problem constants
#define BB 4
#define SS 4096
#define EE 256
#define DD 32

// ---- bf16 mma.sync m16n8k16 (arch-generic PTX -> HMMA on sm_103) ----
__device__ __forceinline__ void mma_bf16(float c[4], const uint32_t a[4],
                                         uint32_t b0, uint32_t b1) {
    asm volatile(
        "mma.sync.aligned.m16n8k16.row.col.f32.bf16.bf16.f32 "
        "{%0,%1,%2,%3}, {%4,%5,%6,%7}, {%8,%9}, {%0,%1,%2,%3};"
        : "+f"(c[0]), "+f"(c[1]), "+f"(c[2]), "+f"(c[3])
        : "r"(a[0]), "r"(a[1]), "r"(a[2]), "r"(a[3]), "r"(b0), "r"(b1));
}
__device__ __forceinline__ uint32_t cvt_bf2(float a, float b) {
    uint32_t r;
    asm("cvt.rn.satfinite.bf16x2.f32 %0, %1, %2;" : "=r"(r) : "f"(b), "f"(a));
    return r;
}
__device__ __forceinline__ float ex2f(float x) {
    float y; asm("ex2.approx.f32 %0, %1;" : "=f"(y) : "f"(x)); return y;
}

// Device scratch.
// Q (pre-scaled by log2e via Wq) / K: hi-lo bf16 splits, [B*S][32] row-major.
// V: PAIRED words: word (s/2)*32+d = {V[s_even][d] lo16, V[s_odd][d] hi16}.
__device__ __nv_bfloat16 g_qh[BB * SS * DD], g_ql[BB * SS * DD];
__device__ __nv_bfloat16 g_kh[BB * SS * DD], g_kl[BB * SS * DD];
__device__ uint32_t g_vph[BB * SS * DD / 2], g_vpl[BB * SS * DD / 2];
// Split-K partials: [half][B*S*D] acc, [half][B*S] denominators.
__device__ float g_pacc[2][BB * SS * DD];
__device__ float g_pl[2][BB * SS];

// ---------------------------------------------------------------------------
// HMMA projection: [q|k|v] = x @ [Wq|Wk|Wv] with split-bf16 (3 mmas/product).
// CTA = 256 threads = 8 warps; 128 rows of x per CTA; N = 96 (3 mats x 32);
// K = 256 in 4 chunks of 64. x and W^T converted to bf16 hi/lo into smem on
// the fly. log2(e) folded into Wq. Outputs stored in the attn layouts.
//
// SMEM words (uint32 = bf16x2 along e):
//   XS : hi @0 (128 x 36-stride), lo @4608
//   WT : hi @9216 (96 n x 36-stride), lo @12672    [n = mat*32 + outcol]
// ---------------------------------------------------------------------------
#define PXH_W 0
#define PXL_W 4608
#define PWH_W 9216
#define PWL_W 12672
#define PROJ_SMEM_BYTES (16128 * 4)

__global__ __launch_bounds__(256, 1) void proj_mma(
    const float* __restrict__ x,
    const float* __restrict__ Wq,
    const float* __restrict__ Wk,
    const float* __restrict__ Wv)
{
    extern __shared__ uint32_t smw[];
    const int tid = threadIdx.x;
    const int wid = tid >> 5, lane = tid & 31;
    const int gid = lane >> 2, tig = lane & 3;
    const int row0 = blockIdx.x * 128;
    const int mrow = wid * 16;

    float c[12][4];
#pragma unroll
    for (int nt = 0; nt < 12; nt++)
#pragma unroll
        for (int j = 0; j < 4; j++) c[nt][j] = 0.f;

    for (int ch = 0; ch < 4; ch++) {
        const int ec = ch * 64;
        __syncthreads();   // previous chunk's mma reads complete

        // ---- W^T chunk: 96 n x 32 words; thread does 12 words ----
#pragma unroll
        for (int it = 0; it < 12; it++) {
            const int u = tid + it * 256;
            const int n = u >> 5, we = u & 31;
            const int mat = n >> 5, d = n & 31;
            const float* Wm = (mat == 0) ? Wq : (mat == 1) ? Wk : Wv;
            const float sc = (mat == 0) ? 1.4426950408889634f : 1.0f;
            const int e0 = ec + 2 * we;
            const float w0 = __ldg(&Wm[e0 * DD + d]) * sc;
            const float w1 = __ldg(&Wm[(e0 + 1) * DD + d]) * sc;
            const uint32_t h = cvt_bf2(w0, w1);
            const float r0 = w0 - __uint_as_float(h << 16);
            const float r1 = w1 - __uint_as_float(h & 0xFFFF0000u);
            smw[PWH_W + n * 36 + we] = h;
            smw[PWL_W + n * 36 + we] = cvt_bf2(r0, r1);
        }

        // ---- x chunk: 128 rows x 64 e; thread does 8 float4 ----
#pragma unroll
        for (int it = 0; it < 8; it++) {
            const int u = tid + it * 256;
            const int r = u >> 4, c4 = u & 15;
            const float4 f = *(const float4*)(x + (size_t)(row0 + r) * EE + ec + c4 * 4);
            const uint32_t h0 = cvt_bf2(f.x, f.y);
            const uint32_t h1 = cvt_bf2(f.z, f.w);
            const float a0 = f.x - __uint_as_float(h0 << 16);
            const float a1 = f.y - __uint_as_float(h0 & 0xFFFF0000u);
            const float a2 = f.z - __uint_as_float(h1 << 16);
            const float a3 = f.w - __uint_as_float(h1 & 0xFFFF0000u);
            const int wbase = r * 36 + c4 * 2;
            *(uint2*)&smw[PXH_W + wbase] = make_uint2(h0, h1);
            *(uint2*)&smw[PXL_W + wbase] = make_uint2(cvt_bf2(a0, a1), cvt_bf2(a2, a3));
        }
        __syncthreads();

        // ---- mma: 4 k-tiles x 12 n-tiles x 3 splits ----
#pragma unroll
        for (int kt = 0; kt < 4; kt++) {
            uint32_t ah[4], al[4];
            const int ra = (mrow + gid) * 36 + kt * 8 + tig;
            const int rb = (mrow + gid + 8) * 36 + kt * 8 + tig;
            ah[0] = smw[PXH_W + ra];     ah[1] = smw[PXH_W + rb];
            ah[2] = smw[PXH_W + ra + 4]; ah[3] = smw[PXH_W + rb + 4];
            al[0] = smw[PXL_W + ra];     al[1] = smw[PXL_W + rb];
            al[2] = smw[PXL_W + ra + 4]; al[3] = smw[PXL_W + rb + 4];
#pragma unroll
            for (int nt = 0; nt < 12; nt++) {
                const int w0 = (nt * 8 + gid) * 36 + kt * 8 + tig;
                const uint32_t bh0 = smw[PWH_W + w0], bh1 = smw[PWH_W + w0 + 4];
                const uint32_t bl0 = smw[PWL_W + w0], bl1 = smw[PWL_W + w0 + 4];
                mma_bf16(c[nt], ah, bh0, bh1);
                mma_bf16(c[nt], ah, bl0, bl1);
                mma_bf16(c[nt], al, bh0, bh1);
            }
        }
    }

    // ---- epilogue: split + store in attn layouts ----
    const int r0 = row0 + mrow + gid, r1 = r0 + 8;
#pragma unroll
    for (int nt = 0; nt < 12; nt++) {
        const int mat = nt >> 2;
        const int col = (nt & 3) * 8 + tig * 2;
        if (mat < 2) {
            // q/k: packed bf16x2 words, [row][col/2]
            uint32_t* dh = (uint32_t*)(mat == 0 ? g_qh : g_kh);
            uint32_t* dl = (uint32_t*)(mat == 0 ? g_ql : g_kl);
            const uint32_t h0 = cvt_bf2(c[nt][0], c[nt][1]);
            const float s00 = c[nt][0] - __uint_as_float(h0 << 16);
            const float s01 = c[nt][1] - __uint_as_float(h0 & 0xFFFF0000u);
            const uint32_t h1 = cvt_bf2(c[nt][2], c[nt][3]);
            const float s10 = c[nt][2] - __uint_as_float(h1 << 16);
            const float s11 = c[nt][3] - __uint_as_float(h1 & 0xFFFF0000u);
            const int wi0 = r0 * 16 + (col >> 1), wi1 = r1 * 16 + (col >> 1);
            dh[wi0] = h0; dl[wi0] = cvt_bf2(s00, s01);
            dh[wi1] = h1; dl[wi1] = cvt_bf2(s10, s11);
        } else {
            // v: paired even/odd-row words, scalar bf16 stores
            __nv_bfloat16* vh = (__nv_bfloat16*)g_vph;
            __nv_bfloat16* vl = (__nv_bfloat16*)g_vpl;
#pragma unroll
            for (int rr = 0; rr < 2; rr++) {
                const int r = rr ? r1 : r0;
#pragma unroll
                for (int cc = 0; cc < 2; cc++) {
                    const float v = c[nt][rr * 2 + cc];
                    const __nv_bfloat16 hb = __float2bfloat16(v);
                    const __nv_bfloat16 lb = __float2bfloat16(v - __bfloat162float(hb));
                    const int idx = ((r >> 1) * DD + col + cc) * 2 + (r & 1);
                    vh[idx] = hb;
                    vl[idx] = lb;
                }
            }
        }
    }
}

// ---------------------------------------------------------------------------
// HMMA flash attention, split-K (unchanged from R13 best).
// ---------------------------------------------------------------------------
#define QPH_W 0
#define QPL_W 2048
#define KBASE_W 4096
#define VBASE_W 9216
#define SMEM_BYTES (14336 * 4)

__global__ __launch_bounds__(256, 2) void attn_mma()
{
    extern __shared__ uint32_t smw[];
    const int tid  = threadIdx.x;
    const int wid  = tid >> 5, lane = tid & 31;
    const int gid  = lane >> 2, tig = lane & 3;
    const int b    = blockIdx.y;
    const int q0   = blockIdx.x * 128;
    const int half = blockIdx.z;
    const int qbase = wid * 16;

    const __nv_bfloat16* khb = g_kh + (size_t)b * SS * DD;
    const __nv_bfloat16* klb = g_kl + (size_t)b * SS * DD;
    const uint32_t* vphb = g_vph + (size_t)b * (SS / 2) * DD;
    const uint32_t* vplb = g_vpl + (size_t)b * (SS / 2) * DD;

    // ---- one-time Q tile load: 128 rows x {hi,lo} = 1024 uint4 ----
#pragma unroll
    for (int it = 0; it < 4; it++) {
        const int u = tid + it * 256;
        const int split = u >> 9, r = (u >> 2) & 127, c4 = u & 3;
        const __nv_bfloat16* src = split ? g_ql : g_qh;
        const uint4 d = *(const uint4*)(src + (size_t)(b * SS + q0 + r) * DD + c4 * 8);
        *(uint4*)&smw[(split ? QPL_W : QPH_W) + r * 16 + c4 * 4] = d;
    }

    // ---- per-thread staged-load coordinates ----
    int k_off[2], k_drel[2];
    const __nv_bfloat16* k_src[2];
    int v_goff[2], v_drel[2];
    const uint32_t* v_src[2];
#pragma unroll
    for (int it = 0; it < 2; it++) {
        const int u = tid + it * 256;
        {
            const int split = u >> 8, r = (u >> 2) & 63, c4 = u & 3;
            k_src[it]  = split ? klb : khb;
            k_off[it]  = r * DD + c4 * 8;
            k_drel[it] = (split ? 1280 : 0) + r * 20 + c4 * 4;
        }
        {
            const int split = u >> 8, k2 = (u >> 3) & 31, nb = u & 7;
            v_src[it]  = split ? vplb : vphb;
            v_goff[it] = k2 * DD + nb * 4;
            v_drel[it] = (split ? 1280 : 0) + k2 * 40 + nb * 4;
        }
    }

    // ---- prologue: first chunk of this half into buffer 0 ----
    const int c0K = half * 32 * 64 * DD;
    const int c0V = half * 32 * 32 * DD;
    uint4 kreg[2], vreg[2];
#pragma unroll
    for (int it = 0; it < 2; it++) {
        kreg[it] = *(const uint4*)(k_src[it] + c0K + k_off[it]);
        vreg[it] = *(const uint4*)(v_src[it] + c0V + v_goff[it]);
    }
#pragma unroll
    for (int it = 0; it < 2; it++) {
        *(uint4*)&smw[KBASE_W + k_drel[it]] = kreg[it];
        *(uint4*)&smw[VBASE_W + v_drel[it]] = vreg[it];
    }
    __syncthreads();

    // ---- Q fragments ----
    uint32_t qf[2][2][4];
#pragma unroll
    for (int s = 0; s < 2; s++)
#pragma unroll
        for (int kt = 0; kt < 2; kt++) {
            const int base = s ? QPL_W : QPH_W;
            qf[s][kt][0] = smw[base + (qbase + gid) * 16 + kt * 8 + tig];
            qf[s][kt][1] = smw[base + (qbase + gid + 8) * 16 + kt * 8 + tig];
            qf[s][kt][2] = smw[base + (qbase + gid) * 16 + kt * 8 + tig + 4];
            qf[s][kt][3] = smw[base + (qbase + gid + 8) * 16 + kt * 8 + tig + 4];
        }

    float acc[4][4];
#pragma unroll
    for (int i = 0; i < 4; i++)
#pragma unroll
        for (int j = 0; j < 4; j++) acc[i][j] = 0.f;
    float l0 = 0.f, l8 = 0.f;

    for (int nc = 0; nc < 32; nc++) {
        const int db = nc & 1;
        const bool pre = (nc + 1 < 32);

        if (pre) {
            const int kcK = c0K + (nc + 1) * 64 * DD;
            const int kcV = c0V + (nc + 1) * 32 * DD;
#pragma unroll
            for (int it = 0; it < 2; it++) {
                kreg[it] = *(const uint4*)(k_src[it] + kcK + k_off[it]);
                vreg[it] = *(const uint4*)(v_src[it] + kcV + v_goff[it]);
            }
        }

        // ---- QK ----
        float c[8][4];
#pragma unroll
        for (int nt = 0; nt < 8; nt++)
#pragma unroll
            for (int j = 0; j < 4; j++) c[nt][j] = 0.f;

        const int kbh = KBASE_W + db * 2560, kbl = kbh + 1280;
#pragma unroll
        for (int kt = 0; kt < 2; kt++)
#pragma unroll
            for (int nt = 0; nt < 8; nt++) {
                const int w0 = (nt * 8 + gid) * 20 + kt * 8 + tig;
                const uint32_t kh0 = smw[kbh + w0], kh1 = smw[kbh + w0 + 4];
                const uint32_t kl0 = smw[kbl + w0], kl1 = smw[kbl + w0 + 4];
                mma_bf16(c[nt], qf[0][kt], kh0, kh1);
                mma_bf16(c[nt], qf[0][kt], kl0, kl1);
                mma_bf16(c[nt], qf[1][kt], kh0, kh1);
            }

        if (pre) {
            const int o2 = (db ^ 1) * 2560;
#pragma unroll
            for (int it = 0; it < 2; it++) {
                *(uint4*)&smw[KBASE_W + o2 + k_drel[it]] = kreg[it];
                *(uint4*)&smw[VBASE_W + o2 + v_drel[it]] = vreg[it];
            }
        }

        // ---- softmax: p = ex2(s), repack to A-frags ----
        uint32_t aph[4][4], apl[4][4];
#pragma unroll
        for (int nt = 0; nt < 8; nt++) {
            const float p0 = ex2f(c[nt][0]);
            const float p1 = ex2f(c[nt][1]);
            const float p2 = ex2f(c[nt][2]);
            const float p3 = ex2f(c[nt][3]);
            l0 += p0 + p1;
            l8 += p2 + p3;
            const uint32_t h01 = cvt_bf2(p0, p1);
            const uint32_t h23 = cvt_bf2(p2, p3);
            const float r0 = p0 - __uint_as_float(h01 << 16);
            const float r1 = p1 - __uint_as_float(h01 & 0xFFFF0000u);
            const float r2 = p2 - __uint_as_float(h23 << 16);
            const float r3 = p3 - __uint_as_float(h23 & 0xFFFF0000u);
            const uint32_t q01 = cvt_bf2(r0, r1);
            const uint32_t q23 = cvt_bf2(r2, r3);
            const int kt2 = nt >> 1, hi = (nt & 1) * 2;
            aph[kt2][hi]     = h01; aph[kt2][hi + 1] = h23;
            apl[kt2][hi]     = q01; apl[kt2][hi + 1] = q23;
        }

        // ---- PV ----
        const int vbh = VBASE_W + db * 2560, vbl = vbh + 1280;
#pragma unroll
        for (int kt2 = 0; kt2 < 4; kt2++)
#pragma unroll
            for (int nt2 = 0; nt2 < 4; nt2++) {
                const int w0 = (kt2 * 8 + tig) * 40 + nt2 * 8 + gid;
                const uint32_t vh0 = smw[vbh + w0], vh1 = smw[vbh + w0 + 160];
                const uint32_t vl0 = smw[vbl + w0], vl1 = smw[vbl + w0 + 160];
                mma_bf16(acc[nt2], aph[kt2], vh0, vh1);
                mma_bf16(acc[nt2], aph[kt2], vl0, vl1);
                mma_bf16(acc[nt2], apl[kt2], vh0, vh1);
            }

        __syncthreads();
    }

    // ---- epilogue: reduce l; write RAW partials ----
    l0 += __shfl_xor_sync(0xffffffffu, l0, 1, 4);
    l0 += __shfl_xor_sync(0xffffffffu, l0, 2, 4);
    l8 += __shfl_xor_sync(0xffffffffu, l8, 1, 4);
    l8 += __shfl_xor_sync(0xffffffffu, l8, 2, 4);

    const size_t row0 = (size_t)b * SS + q0 + qbase + gid;
    float* pa = g_pacc[half];
    if (tig == 0) {
        g_pl[half][row0]     = l0;
        g_pl[half][row0 + 8] = l8;
    }
#pragma unroll
    for (int nt2 = 0; nt2 < 4; nt2++) {
        *(float2*)(pa + row0 * DD + nt2 * 8 + tig * 2) =
            make_float2(acc[nt2][0], acc[nt2][1]);
        *(float2*)(pa + (row0 + 8) * DD + nt2 * 8 + tig * 2) =
            make_float2(acc[nt2][2], acc[nt2][3]);
    }
}

// ---------------------------------------------------------------------------
// Merge: out = (acc0 + acc1) * scaling / (l0 + l1).
// ---------------------------------------------------------------------------
__global__ __launch_bounds__(256, 1) void merge_kernel(float* __restrict__ out)
{
    const int i4 = blockIdx.x * 256 + threadIdx.x;
    const int row = i4 >> 3;
    const float l = g_pl[0][row] + g_pl[1][row];
    const float s = 0.17677669529663687f / l;
    const float4 a = ((const float4*)g_pacc[0])[i4];
    const float4 b = ((const float4*)g_pacc[1])[i4];
    float4 o;
    o.x = (a.x + b.x) * s; o.y = (a.y + b.y) * s;
    o.z = (a.z + b.z) * s; o.w = (a.w + b.w) * s;
    ((float4*)out)[i4] = o;
}

// ---------------------------------------------------------------------------
extern "C" void kernel_launch(void* const* d_in, const int* in_sizes, int n_in,
                              void* d_out, int out_size)
{
    const float* x  = (const float*)d_in[0];
    const float* Wq = (const float*)d_in[1];
    const float* Wk = (const float*)d_in[2];
    const float* Wv = (const float*)d_in[3];
    float* out = (float*)d_out;

    cudaFuncSetAttribute(proj_mma, cudaFuncAttributeMaxDynamicSharedMemorySize, PROJ_SMEM_BYTES);
    proj_mma<<<(BB * SS) / 128, 256, PROJ_SMEM_BYTES>>>(x, Wq, Wk, Wv);

    cudaFuncSetAttribute(attn_mma, cudaFuncAttributeMaxDynamicSharedMemorySize, SMEM_BYTES);
    dim3 grid(SS / 128, BB, 2);
    attn_mma<<<grid, 256, SMEM_BYTES>>>();

    merge_kernel<<<(BB * SS * DD / 4) / 256, 256>>>(out);
}

// round 15
// speedup vs baseline: 1.7049x; 1.0960x over previous
#include <cuda_runtime.h>
#include <cuda_bf16.h>
#include <math_constants.h>
#include <cstdint>

// Problem constants
#define BB 4
#define SS 4096
#define EE 256
#define DD 32

// ---- bf16 mma.sync m16n8k16 (arch-generic PTX -> HMMA on sm_103) ----
__device__ __forceinline__ void mma_bf16(float c[4], const uint32_t a[4],
                                         uint32_t b0, uint32_t b1) {
    asm volatile(
        "mma.sync.aligned.m16n8k16.row.col.f32.bf16.bf16.f32 "
        "{%0,%1,%2,%3}, {%4,%5,%6,%7}, {%8,%9}, {%0,%1,%2,%3};"
        : "+f"(c[0]), "+f"(c[1]), "+f"(c[2]), "+f"(c[3])
        : "r"(a[0]), "r"(a[1]), "r"(a[2]), "r"(a[3]), "r"(b0), "r"(b1));
}
__device__ __forceinline__ uint32_t cvt_bf2(float a, float b) {
    uint32_t r;
    asm("cvt.rn.satfinite.bf16x2.f32 %0, %1, %2;" : "=r"(r) : "f"(b), "f"(a));
    return r;
}
__device__ __forceinline__ float ex2f(float x) {
    float y; asm("ex2.approx.f32 %0, %1;" : "=f"(y) : "f"(x)); return y;
}

// Device scratch.
// Q (pre-scaled by log2e via Wq) / K: hi-lo bf16 splits, [B*S][32] row-major.
// V: PAIRED words: word (s/2)*32+d = {V[s_even][d] lo16, V[s_odd][d] hi16}.
__device__ __nv_bfloat16 g_qh[BB * SS * DD], g_ql[BB * SS * DD];
__device__ __nv_bfloat16 g_kh[BB * SS * DD], g_kl[BB * SS * DD];
__device__ uint32_t g_vph[BB * SS * DD / 2], g_vpl[BB * SS * DD / 2];
// Split-K partials: [half][B*S*D] acc, [half][B*S] denominators.
__device__ float g_pacc[2][BB * SS * DD];
__device__ float g_pl[2][BB * SS];

// ---------------------------------------------------------------------------
// HMMA projection v2: [q|k|v] = x @ [Wq|Wk|Wv], split-bf16 (3 mmas/product).
// CTA = 256 threads = 8 warps = 4 m-tiles x 2 n-groups (6 n-tiles each).
// 64 rows of x per CTA -> 256 CTAs, 2 resident/SM. K = 256 in 4 chunks of 64,
// register-staged prefetch (LDG hidden under mma). Coalesced W loads
// (lane-fastest = output col d). log2(e) folded into Wq.
//
// SMEM words (uint32 = bf16x2 along e):
//   XS : hi @0 (64 x 36-stride), lo @2304
//   WT : hi @4608 (96 n x 36-stride), lo @8064    [n = mat*32 + d]
// ---------------------------------------------------------------------------
#define PXH_W 0
#define PXL_W 2304
#define PWH_W 4608
#define PWL_W 8064
#define PROJ_SMEM_BYTES (11520 * 4)

__global__ __launch_bounds__(256, 2) void proj_mma(
    const float* __restrict__ x,
    const float* __restrict__ Wq,
    const float* __restrict__ Wk,
    const float* __restrict__ Wv)
{
    extern __shared__ uint32_t smw[];
    const int tid = threadIdx.x;
    const int wid = tid >> 5, lane = tid & 31;
    const int gid = lane >> 2, tig = lane & 3;
    const int row0 = blockIdx.x * 64;
    const int mt = wid & 3;           // m-tile (16 rows)
    const int ng = wid >> 2;          // n-group (6 n-tiles)
    const int mrow = mt * 16;

    // ---- W-load coordinates: lane-fastest d -> coalesced LDG ----
    const float* w_src[12];
    int w_goff[12], w_n[12];
    float w_sc[12];
#pragma unroll
    for (int it = 0; it < 12; it++) {
        const int u = tid + it * 256;
        const int d = u & 31, rest = u >> 5;       // rest in [0,96)
        const int mat = rest % 3, we = rest / 3;   // we in [0,32)
        w_src[it]  = (mat == 0) ? Wq : (mat == 1) ? Wk : Wv;
        w_sc[it]   = (mat == 0) ? 1.4426950408889634f : 1.0f;
        w_goff[it] = (2 * we) * DD + d;            // + ec*DD per chunk
        w_n[it]    = (mat * 32 + d) * 36 + we;
    }
    // x-load coordinates: 64 rows x 16 float4 -> 4 per thread
    int x_r[4], x_c4[4];
#pragma unroll
    for (int it = 0; it < 4; it++) {
        const int u = tid + it * 256;
        x_r[it] = u >> 4; x_c4[it] = u & 15;
    }

    // ---- prologue: stage chunk 0 into registers ----
    float2 wreg[12];
    float4 xreg[4];
#pragma unroll
    for (int it = 0; it < 12; it++) {
        wreg[it].x = __ldg(w_src[it] + w_goff[it]) * w_sc[it];
        wreg[it].y = __ldg(w_src[it] + w_goff[it] + DD) * w_sc[it];
    }
#pragma unroll
    for (int it = 0; it < 4; it++)
        xreg[it] = *(const float4*)(x + (size_t)(row0 + x_r[it]) * EE + x_c4[it] * 4);

    float acc[6][4];
#pragma unroll
    for (int nt = 0; nt < 6; nt++)
#pragma unroll
        for (int j = 0; j < 4; j++) acc[nt][j] = 0.f;

    for (int ch = 0; ch < 4; ch++) {
        if (ch) __syncthreads();   // previous chunk's mma reads complete

        // ---- commit staged chunk to smem (cvt + split) ----
#pragma unroll
        for (int it = 0; it < 12; it++) {
            const uint32_t h = cvt_bf2(wreg[it].x, wreg[it].y);
            const float r0 = wreg[it].x - __uint_as_float(h << 16);
            const float r1 = wreg[it].y - __uint_as_float(h & 0xFFFF0000u);
            smw[PWH_W + w_n[it]] = h;
            smw[PWL_W + w_n[it]] = cvt_bf2(r0, r1);
        }
#pragma unroll
        for (int it = 0; it < 4; it++) {
            const float4 f = xreg[it];
            const uint32_t h0 = cvt_bf2(f.x, f.y);
            const uint32_t h1 = cvt_bf2(f.z, f.w);
            const float a0 = f.x - __uint_as_float(h0 << 16);
            const float a1 = f.y - __uint_as_float(h0 & 0xFFFF0000u);
            const float a2 = f.z - __uint_as_float(h1 << 16);
            const float a3 = f.w - __uint_as_float(h1 & 0xFFFF0000u);
            const int wbase = x_r[it] * 36 + x_c4[it] * 2;
            *(uint2*)&smw[PXH_W + wbase] = make_uint2(h0, h1);
            *(uint2*)&smw[PXL_W + wbase] = make_uint2(cvt_bf2(a0, a1), cvt_bf2(a2, a3));
        }
        __syncthreads();

        // ---- prefetch next chunk into registers (hidden under mma) ----
        if (ch + 1 < 4) {
            const int ecn = (ch + 1) * 64;
#pragma unroll
            for (int it = 0; it < 12; it++) {
                wreg[it].x = __ldg(w_src[it] + ecn * DD + w_goff[it]) * w_sc[it];
                wreg[it].y = __ldg(w_src[it] + ecn * DD + w_goff[it] + DD) * w_sc[it];
            }
#pragma unroll
            for (int it = 0; it < 4; it++)
                xreg[it] = *(const float4*)(x + (size_t)(row0 + x_r[it]) * EE + ecn + x_c4[it] * 4);
        }

        // ---- mma: 4 k-tiles x 6 n-tiles x 3 splits ----
#pragma unroll
        for (int kt = 0; kt < 4; kt++) {
            uint32_t ah[4], al[4];
            const int ra = (mrow + gid) * 36 + kt * 8 + tig;
            const int rb = (mrow + gid + 8) * 36 + kt * 8 + tig;
            ah[0] = smw[PXH_W + ra];     ah[1] = smw[PXH_W + rb];
            ah[2] = smw[PXH_W + ra + 4]; ah[3] = smw[PXH_W + rb + 4];
            al[0] = smw[PXL_W + ra];     al[1] = smw[PXL_W + rb];
            al[2] = smw[PXL_W + ra + 4]; al[3] = smw[PXL_W + rb + 4];
#pragma unroll
            for (int j = 0; j < 6; j++) {
                const int nt = ng * 6 + j;
                const int w0 = (nt * 8 + gid) * 36 + kt * 8 + tig;
                const uint32_t bh0 = smw[PWH_W + w0], bh1 = smw[PWH_W + w0 + 4];
                const uint32_t bl0 = smw[PWL_W + w0], bl1 = smw[PWL_W + w0 + 4];
                mma_bf16(acc[j], ah, bh0, bh1);
                mma_bf16(acc[j], ah, bl0, bl1);
                mma_bf16(acc[j], al, bh0, bh1);
            }
        }
    }

    // ---- epilogue: split + store in attn layouts ----
    const int r0 = row0 + mrow + gid, r1 = r0 + 8;
#pragma unroll
    for (int j = 0; j < 6; j++) {
        const int nt = ng * 6 + j;
        const int mat = nt >> 2;
        const int col = (nt & 3) * 8 + tig * 2;
        if (mat < 2) {
            uint32_t* dh = (uint32_t*)(mat == 0 ? g_qh : g_kh);
            uint32_t* dl = (uint32_t*)(mat == 0 ? g_ql : g_kl);
            const uint32_t h0 = cvt_bf2(acc[j][0], acc[j][1]);
            const float s00 = acc[j][0] - __uint_as_float(h0 << 16);
            const float s01 = acc[j][1] - __uint_as_float(h0 & 0xFFFF0000u);
            const uint32_t h1 = cvt_bf2(acc[j][2], acc[j][3]);
            const float s10 = acc[j][2] - __uint_as_float(h1 << 16);
            const float s11 = acc[j][3] - __uint_as_float(h1 & 0xFFFF0000u);
            const int wi0 = r0 * 16 + (col >> 1), wi1 = r1 * 16 + (col >> 1);
            dh[wi0] = h0; dl[wi0] = cvt_bf2(s00, s01);
            dh[wi1] = h1; dl[wi1] = cvt_bf2(s10, s11);
        } else {
            __nv_bfloat16* vh = (__nv_bfloat16*)g_vph;
            __nv_bfloat16* vl = (__nv_bfloat16*)g_vpl;
#pragma unroll
            for (int rr = 0; rr < 2; rr++) {
                const int r = rr ? r1 : r0;
#pragma unroll
                for (int cc = 0; cc < 2; cc++) {
                    const float v = acc[j][rr * 2 + cc];
                    const __nv_bfloat16 hb = __float2bfloat16(v);
                    const __nv_bfloat16 lb = __float2bfloat16(v - __bfloat162float(hb));
                    const int idx = ((r >> 1) * DD + col + cc) * 2 + (r & 1);
                    vh[idx] = hb;
                    vl[idx] = lb;
                }
            }
        }
    }
}

// ---------------------------------------------------------------------------
// HMMA flash attention, split-K (unchanged from R13/R14 best).
// ---------------------------------------------------------------------------
#define QPH_W 0
#define QPL_W 2048
#define KBASE_W 4096
#define VBASE_W 9216
#define SMEM_BYTES (14336 * 4)

__global__ __launch_bounds__(256, 2) void attn_mma()
{
    extern __shared__ uint32_t smw[];
    const int tid  = threadIdx.x;
    const int wid  = tid >> 5, lane = tid & 31;
    const int gid  = lane >> 2, tig = lane & 3;
    const int b    = blockIdx.y;
    const int q0   = blockIdx.x * 128;
    const int half = blockIdx.z;
    const int qbase = wid * 16;

    const __nv_bfloat16* khb = g_kh + (size_t)b * SS * DD;
    const __nv_bfloat16* klb = g_kl + (size_t)b * SS * DD;
    const uint32_t* vphb = g_vph + (size_t)b * (SS / 2) * DD;
    const uint32_t* vplb = g_vpl + (size_t)b * (SS / 2) * DD;

    // ---- one-time Q tile load: 128 rows x {hi,lo} = 1024 uint4 ----
#pragma unroll
    for (int it = 0; it < 4; it++) {
        const int u = tid + it * 256;
        const int split = u >> 9, r = (u >> 2) & 127, c4 = u & 3;
        const __nv_bfloat16* src = split ? g_ql : g_qh;
        const uint4 d = *(const uint4*)(src + (size_t)(b * SS + q0 + r) * DD + c4 * 8);
        *(uint4*)&smw[(split ? QPL_W : QPH_W) + r * 16 + c4 * 4] = d;
    }

    // ---- per-thread staged-load coordinates ----
    int k_off[2], k_drel[2];
    const __nv_bfloat16* k_src[2];
    int v_goff[2], v_drel[2];
    const uint32_t* v_src[2];
#pragma unroll
    for (int it = 0; it < 2; it++) {
        const int u = tid + it * 256;
        {
            const int split = u >> 8, r = (u >> 2) & 63, c4 = u & 3;
            k_src[it]  = split ? klb : khb;
            k_off[it]  = r * DD + c4 * 8;
            k_drel[it] = (split ? 1280 : 0) + r * 20 + c4 * 4;
        }
        {
            const int split = u >> 8, k2 = (u >> 3) & 31, nb = u & 7;
            v_src[it]  = split ? vplb : vphb;
            v_goff[it] = k2 * DD + nb * 4;
            v_drel[it] = (split ? 1280 : 0) + k2 * 40 + nb * 4;
        }
    }

    // ---- prologue: first chunk of this half into buffer 0 ----
    const int c0K = half * 32 * 64 * DD;
    const int c0V = half * 32 * 32 * DD;
    uint4 kreg[2], vreg[2];
#pragma unroll
    for (int it = 0; it < 2; it++) {
        kreg[it] = *(const uint4*)(k_src[it] + c0K + k_off[it]);
        vreg[it] = *(const uint4*)(v_src[it] + c0V + v_goff[it]);
    }
#pragma unroll
    for (int it = 0; it < 2; it++) {
        *(uint4*)&smw[KBASE_W + k_drel[it]] = kreg[it];
        *(uint4*)&smw[VBASE_W + v_drel[it]] = vreg[it];
    }
    __syncthreads();

    // ---- Q fragments ----
    uint32_t qf[2][2][4];
#pragma unroll
    for (int s = 0; s < 2; s++)
#pragma unroll
        for (int kt = 0; kt < 2; kt++) {
            const int base = s ? QPL_W : QPH_W;
            qf[s][kt][0] = smw[base + (qbase + gid) * 16 + kt * 8 + tig];
            qf[s][kt][1] = smw[base + (qbase + gid + 8) * 16 + kt * 8 + tig];
            qf[s][kt][2] = smw[base + (qbase + gid) * 16 + kt * 8 + tig + 4];
            qf[s][kt][3] = smw[base + (qbase + gid + 8) * 16 + kt * 8 + tig + 4];
        }

    float acc[4][4];
#pragma unroll
    for (int i = 0; i < 4; i++)
#pragma unroll
        for (int j = 0; j < 4; j++) acc[i][j] = 0.f;
    float l0 = 0.f, l8 = 0.f;

    for (int nc = 0; nc < 32; nc++) {
        const int db = nc & 1;
        const bool pre = (nc + 1 < 32);

        if (pre) {
            const int kcK = c0K + (nc + 1) * 64 * DD;
            const int kcV = c0V + (nc + 1) * 32 * DD;
#pragma unroll
            for (int it = 0; it < 2; it++) {
                kreg[it] = *(const uint4*)(k_src[it] + kcK + k_off[it]);
                vreg[it] = *(const uint4*)(v_src[it] + kcV + v_goff[it]);
            }
        }

        // ---- QK ----
        float c[8][4];
#pragma unroll
        for (int nt = 0; nt < 8; nt++)
#pragma unroll
            for (int j = 0; j < 4; j++) c[nt][j] = 0.f;

        const int kbh = KBASE_W + db * 2560, kbl = kbh + 1280;
#pragma unroll
        for (int kt = 0; kt < 2; kt++)
#pragma unroll
            for (int nt = 0; nt < 8; nt++) {
                const int w0 = (nt * 8 + gid) * 20 + kt * 8 + tig;
                const uint32_t kh0 = smw[kbh + w0], kh1 = smw[kbh + w0 + 4];
                const uint32_t kl0 = smw[kbl + w0], kl1 = smw[kbl + w0 + 4];
                mma_bf16(c[nt], qf[0][kt], kh0, kh1);
                mma_bf16(c[nt], qf[0][kt], kl0, kl1);
                mma_bf16(c[nt], qf[1][kt], kh0, kh1);
            }

        if (pre) {
            const int o2 = (db ^ 1) * 2560;
#pragma unroll
            for (int it = 0; it < 2; it++) {
                *(uint4*)&smw[KBASE_W + o2 + k_drel[it]] = kreg[it];
                *(uint4*)&smw[VBASE_W + o2 + v_drel[it]] = vreg[it];
            }
        }

        // ---- softmax: p = ex2(s), repack to A-frags ----
        uint32_t aph[4][4], apl[4][4];
#pragma unroll
        for (int nt = 0; nt < 8; nt++) {
            const float p0 = ex2f(c[nt][0]);
            const float p1 = ex2f(c[nt][1]);
            const float p2 = ex2f(c[nt][2]);
            const float p3 = ex2f(c[nt][3]);
            l0 += p0 + p1;
            l8 += p2 + p3;
            const uint32_t h01 = cvt_bf2(p0, p1);
            const uint32_t h23 = cvt_bf2(p2, p3);
            const float r0 = p0 - __uint_as_float(h01 << 16);
            const float r1 = p1 - __uint_as_float(h01 & 0xFFFF0000u);
            const float r2 = p2 - __uint_as_float(h23 << 16);
            const float r3 = p3 - __uint_as_float(h23 & 0xFFFF0000u);
            const uint32_t q01 = cvt_bf2(r0, r1);
            const uint32_t q23 = cvt_bf2(r2, r3);
            const int kt2 = nt >> 1, hi = (nt & 1) * 2;
            aph[kt2][hi]     = h01; aph[kt2][hi + 1] = h23;
            apl[kt2][hi]     = q01; apl[kt2][hi + 1] = q23;
        }

        // ---- PV ----
        const int vbh = VBASE_W + db * 2560, vbl = vbh + 1280;
#pragma unroll
        for (int kt2 = 0; kt2 < 4; kt2++)
#pragma unroll
            for (int nt2 = 0; nt2 < 4; nt2++) {
                const int w0 = (kt2 * 8 + tig) * 40 + nt2 * 8 + gid;
                const uint32_t vh0 = smw[vbh + w0], vh1 = smw[vbh + w0 + 160];
                const uint32_t vl0 = smw[vbl + w0], vl1 = smw[vbl + w0 + 160];
                mma_bf16(acc[nt2], aph[kt2], vh0, vh1);
                mma_bf16(acc[nt2], aph[kt2], vl0, vl1);
                mma_bf16(acc[nt2], apl[kt2], vh0, vh1);
            }

        __syncthreads();
    }

    // ---- epilogue: reduce l; write RAW partials ----
    l0 += __shfl_xor_sync(0xffffffffu, l0, 1, 4);
    l0 += __shfl_xor_sync(0xffffffffu, l0, 2, 4);
    l8 += __shfl_xor_sync(0xffffffffu, l8, 1, 4);
    l8 += __shfl_xor_sync(0xffffffffu, l8, 2, 4);

    const size_t row0 = (size_t)b * SS + q0 + qbase + gid;
    float* pa = g_pacc[half];
    if (tig == 0) {
        g_pl[half][row0]     = l0;
        g_pl[half][row0 + 8] = l8;
    }
#pragma unroll
    for (int nt2 = 0; nt2 < 4; nt2++) {
        *(float2*)(pa + row0 * DD + nt2 * 8 + tig * 2) =
            make_float2(acc[nt2][0], acc[nt2][1]);
        *(float2*)(pa + (row0 + 8) * DD + nt2 * 8 + tig * 2) =
            make_float2(acc[nt2][2], acc[nt2][3]);
    }
}

// ---------------------------------------------------------------------------
// Merge: out = (acc0 + acc1) * scaling / (l0 + l1).
// ---------------------------------------------------------------------------
__global__ __launch_bounds__(256, 1) void merge_kernel(float* __restrict__ out)
{
    const int i4 = blockIdx.x * 256 + threadIdx.x;
    const int row = i4 >> 3;
    const float l = g_pl[0][row] + g_pl[1][row];
    const float s = 0.17677669529663687f / l;
    const float4 a = ((const float4*)g_pacc[0])[i4];
    const float4 b = ((const float4*)g_pacc[1])[i4];
    float4 o;
    o.x = (a.x + b.x) * s; o.y = (a.y + b.y) * s;
    o.z = (a.z + b.z) * s; o.w = (a.w + b.w) * s;
    ((float4*)out)[i4] = o;
}

// ---------------------------------------------------------------------------
extern "C" void kernel_launch(void* const* d_in, const int* in_sizes, int n_in,
                              void* d_out, int out_size)
{
    const float* x  = (const float*)d_in[0];
    const float* Wq = (const float*)d_in[1];
    const float* Wk = (const float*)d_in[2];
    const float* Wv = (const float*)d_in[3];
    float* out = (float*)d_out;

    cudaFuncSetAttribute(proj_mma, cudaFuncAttributeMaxDynamicSharedMemorySize, PROJ_SMEM_BYTES);
    proj_mma<<<(BB * SS) / 64, 256, PROJ_SMEM_BYTES>>>(x, Wq, Wk, Wv);

    cudaFuncSetAttribute(attn_mma, cudaFuncAttributeMaxDynamicSharedMemorySize, SMEM_BYTES);
    dim3 grid(SS / 128, BB, 2);
    attn_mma<<<grid, 256, SMEM_BYTES>>>();

    merge_kernel<<<(BB * SS * DD / 4) / 256, 256>>>(out);
}

// round 16
// speedup vs baseline: 1.8068x; 1.0598x over previous
#include <cuda_runtime.h>
#include <cuda_bf16.h>
#include <math_constants.h>
#include <cstdint>

// Problem constants
#define BB 4
#define SS 4096
#define EE 256
#define DD 32

// ---- bf16 mma.sync m16n8k16 (arch-generic PTX -> HMMA on sm_103) ----
__device__ __forceinline__ void mma_bf16(float c[4], const uint32_t a[4],
                                         uint32_t b0, uint32_t b1) {
    asm volatile(
        "mma.sync.aligned.m16n8k16.row.col.f32.bf16.bf16.f32 "
        "{%0,%1,%2,%3}, {%4,%5,%6,%7}, {%8,%9}, {%0,%1,%2,%3};"
        : "+f"(c[0]), "+f"(c[1]), "+f"(c[2]), "+f"(c[3])
        : "r"(a[0]), "r"(a[1]), "r"(a[2]), "r"(a[3]), "r"(b0), "r"(b1));
}
__device__ __forceinline__ void ldsm_x4(uint32_t& r0, uint32_t& r1,
                                        uint32_t& r2, uint32_t& r3, uint32_t addr) {
    asm volatile("ldmatrix.sync.aligned.m8n8.x4.shared.b16 {%0,%1,%2,%3}, [%4];"
        : "=r"(r0), "=r"(r1), "=r"(r2), "=r"(r3) : "r"(addr));
}
__device__ __forceinline__ uint32_t smem_u32(const void* p) {
    uint32_t a;
    asm("{ .reg .u64 t; cvta.to.shared.u64 t, %1; cvt.u32.u64 %0, t; }" : "=r"(a) : "l"(p));
    return a;
}
__device__ __forceinline__ uint32_t cvt_bf2(float a, float b) {
    uint32_t r;
    asm("cvt.rn.satfinite.bf16x2.f32 %0, %1, %2;" : "=r"(r) : "f"(b), "f"(a));
    return r;
}
__device__ __forceinline__ float ex2f(float x) {
    float y; asm("ex2.approx.f32 %0, %1;" : "=f"(y) : "f"(x)); return y;
}

// Device scratch.
// Q (pre-scaled by log2e via Wq) / K: hi-lo bf16 splits, [B*S][32] row-major.
// V: paired-TRANSPOSED words: word (b*32+d)*2048 + s2 = {V[2s2][d], V[2s2+1][d]}.
__device__ __nv_bfloat16 g_qh[BB * SS * DD], g_ql[BB * SS * DD];
__device__ __nv_bfloat16 g_kh[BB * SS * DD], g_kl[BB * SS * DD];
__device__ uint32_t g_vph[BB * DD * SS / 2], g_vpl[BB * DD * SS / 2];
// Split-K partials: [half][B*S*D] acc, [half][B*S] denominators.
__device__ float g_pacc[2][BB * SS * DD];
__device__ float g_pl[2][BB * SS];

// ---------------------------------------------------------------------------
// HMMA projection (R15-proven): [q|k|v] = x @ [Wq|Wk|Wv], split-bf16.
// 64 rows/CTA -> 256 CTAs, 2 resident/SM; coalesced W loads; reg prefetch.
// ---------------------------------------------------------------------------
#define PXH_W 0
#define PXL_W 2304
#define PWH_W 4608
#define PWL_W 8064
#define PROJ_SMEM_BYTES (11520 * 4)

__global__ __launch_bounds__(256, 2) void proj_mma(
    const float* __restrict__ x,
    const float* __restrict__ Wq,
    const float* __restrict__ Wk,
    const float* __restrict__ Wv)
{
    extern __shared__ uint32_t smw[];
    const int tid = threadIdx.x;
    const int wid = tid >> 5, lane = tid & 31;
    const int gid = lane >> 2, tig = lane & 3;
    const int row0 = blockIdx.x * 64;
    const int mt = wid & 3;
    const int ng = wid >> 2;
    const int mrow = mt * 16;

    const float* w_src[12];
    int w_goff[12], w_n[12];
    float w_sc[12];
#pragma unroll
    for (int it = 0; it < 12; it++) {
        const int u = tid + it * 256;
        const int d = u & 31, rest = u >> 5;
        const int mat = rest % 3, we = rest / 3;
        w_src[it]  = (mat == 0) ? Wq : (mat == 1) ? Wk : Wv;
        w_sc[it]   = (mat == 0) ? 1.4426950408889634f : 1.0f;
        w_goff[it] = (2 * we) * DD + d;
        w_n[it]    = (mat * 32 + d) * 36 + we;
    }
    int x_r[4], x_c4[4];
#pragma unroll
    for (int it = 0; it < 4; it++) {
        const int u = tid + it * 256;
        x_r[it] = u >> 4; x_c4[it] = u & 15;
    }

    float2 wreg[12];
    float4 xreg[4];
#pragma unroll
    for (int it = 0; it < 12; it++) {
        wreg[it].x = __ldg(w_src[it] + w_goff[it]) * w_sc[it];
        wreg[it].y = __ldg(w_src[it] + w_goff[it] + DD) * w_sc[it];
    }
#pragma unroll
    for (int it = 0; it < 4; it++)
        xreg[it] = *(const float4*)(x + (size_t)(row0 + x_r[it]) * EE + x_c4[it] * 4);

    float acc[6][4];
#pragma unroll
    for (int nt = 0; nt < 6; nt++)
#pragma unroll
        for (int j = 0; j < 4; j++) acc[nt][j] = 0.f;

    for (int ch = 0; ch < 4; ch++) {
        if (ch) __syncthreads();

#pragma unroll
        for (int it = 0; it < 12; it++) {
            const uint32_t h = cvt_bf2(wreg[it].x, wreg[it].y);
            const float r0 = wreg[it].x - __uint_as_float(h << 16);
            const float r1 = wreg[it].y - __uint_as_float(h & 0xFFFF0000u);
            smw[PWH_W + w_n[it]] = h;
            smw[PWL_W + w_n[it]] = cvt_bf2(r0, r1);
        }
#pragma unroll
        for (int it = 0; it < 4; it++) {
            const float4 f = xreg[it];
            const uint32_t h0 = cvt_bf2(f.x, f.y);
            const uint32_t h1 = cvt_bf2(f.z, f.w);
            const float a0 = f.x - __uint_as_float(h0 << 16);
            const float a1 = f.y - __uint_as_float(h0 & 0xFFFF0000u);
            const float a2 = f.z - __uint_as_float(h1 << 16);
            const float a3 = f.w - __uint_as_float(h1 & 0xFFFF0000u);
            const int wbase = x_r[it] * 36 + x_c4[it] * 2;
            *(uint2*)&smw[PXH_W + wbase] = make_uint2(h0, h1);
            *(uint2*)&smw[PXL_W + wbase] = make_uint2(cvt_bf2(a0, a1), cvt_bf2(a2, a3));
        }
        __syncthreads();

        if (ch + 1 < 4) {
            const int ecn = (ch + 1) * 64;
#pragma unroll
            for (int it = 0; it < 12; it++) {
                wreg[it].x = __ldg(w_src[it] + ecn * DD + w_goff[it]) * w_sc[it];
                wreg[it].y = __ldg(w_src[it] + ecn * DD + w_goff[it] + DD) * w_sc[it];
            }
#pragma unroll
            for (int it = 0; it < 4; it++)
                xreg[it] = *(const float4*)(x + (size_t)(row0 + x_r[it]) * EE + ecn + x_c4[it] * 4);
        }

#pragma unroll
        for (int kt = 0; kt < 4; kt++) {
            uint32_t ah[4], al[4];
            const int ra = (mrow + gid) * 36 + kt * 8 + tig;
            const int rb = (mrow + gid + 8) * 36 + kt * 8 + tig;
            ah[0] = smw[PXH_W + ra];     ah[1] = smw[PXH_W + rb];
            ah[2] = smw[PXH_W + ra + 4]; ah[3] = smw[PXH_W + rb + 4];
            al[0] = smw[PXL_W + ra];     al[1] = smw[PXL_W + rb];
            al[2] = smw[PXL_W + ra + 4]; al[3] = smw[PXL_W + rb + 4];
#pragma unroll
            for (int j = 0; j < 6; j++) {
                const int nt = ng * 6 + j;
                const int w0 = (nt * 8 + gid) * 36 + kt * 8 + tig;
                const uint32_t bh0 = smw[PWH_W + w0], bh1 = smw[PWH_W + w0 + 4];
                const uint32_t bl0 = smw[PWL_W + w0], bl1 = smw[PWL_W + w0 + 4];
                mma_bf16(acc[j], ah, bh0, bh1);
                mma_bf16(acc[j], ah, bl0, bl1);
                mma_bf16(acc[j], al, bh0, bh1);
            }
        }
    }

    // ---- epilogue: split + store in attn layouts ----
    const int r0 = row0 + mrow + gid, r1 = r0 + 8;
#pragma unroll
    for (int j = 0; j < 6; j++) {
        const int nt = ng * 6 + j;
        const int mat = nt >> 2;
        const int col = (nt & 3) * 8 + tig * 2;
        if (mat < 2) {
            uint32_t* dh = (uint32_t*)(mat == 0 ? g_qh : g_kh);
            uint32_t* dl = (uint32_t*)(mat == 0 ? g_ql : g_kl);
            const uint32_t h0 = cvt_bf2(acc[j][0], acc[j][1]);
            const float s00 = acc[j][0] - __uint_as_float(h0 << 16);
            const float s01 = acc[j][1] - __uint_as_float(h0 & 0xFFFF0000u);
            const uint32_t h1 = cvt_bf2(acc[j][2], acc[j][3]);
            const float s10 = acc[j][2] - __uint_as_float(h1 << 16);
            const float s11 = acc[j][3] - __uint_as_float(h1 & 0xFFFF0000u);
            const int wi0 = r0 * 16 + (col >> 1), wi1 = r1 * 16 + (col >> 1);
            dh[wi0] = h0; dl[wi0] = cvt_bf2(s00, s01);
            dh[wi1] = h1; dl[wi1] = cvt_bf2(s10, s11);
        } else {
            // v: transposed paired layout: word (b*32+d)*2048 + s/2, half (s&1)
            __nv_bfloat16* vh = (__nv_bfloat16*)g_vph;
            __nv_bfloat16* vl = (__nv_bfloat16*)g_vpl;
#pragma unroll
            for (int rr = 0; rr < 2; rr++) {
                const int r = rr ? r1 : r0;
                const int b2 = r >> 12, s = r & (SS - 1);
#pragma unroll
                for (int cc = 0; cc < 2; cc++) {
                    const float v = acc[j][rr * 2 + cc];
                    const __nv_bfloat16 hb = __float2bfloat16(v);
                    const __nv_bfloat16 lb = __float2bfloat16(v - __bfloat162float(hb));
                    const int widx = ((b2 * DD + col + cc) << 11) + (s >> 1);
                    vh[widx * 2 + (s & 1)] = hb;
                    vl[widx * 2 + (s & 1)] = lb;
                }
            }
        }
    }
}

// ---------------------------------------------------------------------------
// HMMA flash attention, split-K, ldmatrix fragment loads.
// SMEM words: Q hi@0/lo@2048 (r*16+d2); K 2 bufs @4096+db*2560
// (hi 64x20-stride, lo +1280); V 2 bufs @9216+db*2560 (hi 32 d-rows x
// 36-stride of k2 words, lo +1280).
// ---------------------------------------------------------------------------
#define QPH_W 0
#define QPL_W 2048
#define KBASE_W 4096
#define VBASE_W 9216
#define SMEM_BYTES (14336 * 4)

__global__ __launch_bounds__(256, 2) void attn_mma()
{
    extern __shared__ uint32_t smw[];
    const int tid  = threadIdx.x;
    const int wid  = tid >> 5, lane = tid & 31;
    const int gid  = lane >> 2, tig = lane & 3;
    const int b    = blockIdx.y;
    const int q0   = blockIdx.x * 128;
    const int half = blockIdx.z;
    const int qbase = wid * 16;

    const __nv_bfloat16* khb = g_kh + (size_t)b * SS * DD;
    const __nv_bfloat16* klb = g_kl + (size_t)b * SS * DD;

    // ---- one-time Q tile load ----
#pragma unroll
    for (int it = 0; it < 4; it++) {
        const int u = tid + it * 256;
        const int split = u >> 9, r = (u >> 2) & 127, c4 = u & 3;
        const __nv_bfloat16* src = split ? g_ql : g_qh;
        const uint4 d = *(const uint4*)(src + (size_t)(b * SS + q0 + r) * DD + c4 * 8);
        *(uint4*)&smw[(split ? QPL_W : QPH_W) + r * 16 + c4 * 4] = d;
    }

    // ---- staged-load coordinates ----
    int k_off[2], k_drel[2];
    const __nv_bfloat16* k_src[2];
    int v_goff[2], v_drel[2];
    const uint32_t* v_src[2];
#pragma unroll
    for (int it = 0; it < 2; it++) {
        const int u = tid + it * 256;
        {
            const int split = u >> 8, r = (u >> 2) & 63, c4 = u & 3;
            k_src[it]  = split ? klb : khb;
            k_off[it]  = r * DD + c4 * 8;
            k_drel[it] = (split ? 1280 : 0) + r * 20 + c4 * 4;
        }
        {
            const int split = u >> 8, d = (u >> 3) & 31, k2g = u & 7;
            v_src[it]  = (split ? g_vpl : g_vph) + (size_t)b * DD * (SS / 2);
            v_goff[it] = d * (SS / 2) + k2g * 4;       // word offset, + chunk*32
            v_drel[it] = (split ? 1280 : 0) + d * 36 + k2g * 4;
        }
    }

    // ---- ldmatrix per-lane base addresses (bytes) ----
    const uint32_t smbase = smem_u32(smw);
    const int lj = lane >> 3, lr = lane & 7;
    const uint32_t qk_lane = smbase + (uint32_t)(KBASE_W + lr * 20 + (lj & 1) * 4 + (lj >> 1) * 1280) * 4;
    const uint32_t pv_lane = smbase + (uint32_t)(VBASE_W + lr * 36 + (lj & 1) * 4 + (lj >> 1) * 1280) * 4;

    // ---- prologue: first chunk of this half into buffer 0 ----
    const int c0K = half * 32 * 64 * DD;     // bf16 elements
    const int c0V = half * 32 * 32;          // words (32 k2 per chunk)
    uint4 kreg[2], vreg[2];
#pragma unroll
    for (int it = 0; it < 2; it++) {
        kreg[it] = *(const uint4*)(k_src[it] + c0K + k_off[it]);
        vreg[it] = *(const uint4*)(v_src[it] + c0V + v_goff[it]);
    }
#pragma unroll
    for (int it = 0; it < 2; it++) {
        *(uint4*)&smw[KBASE_W + k_drel[it]] = kreg[it];
        *(uint4*)&smw[VBASE_W + v_drel[it]] = vreg[it];
    }
    __syncthreads();

    // ---- Q fragments ----
    uint32_t qf[2][2][4];
#pragma unroll
    for (int s = 0; s < 2; s++)
#pragma unroll
        for (int kt = 0; kt < 2; kt++) {
            const int base = s ? QPL_W : QPH_W;
            qf[s][kt][0] = smw[base + (qbase + gid) * 16 + kt * 8 + tig];
            qf[s][kt][1] = smw[base + (qbase + gid + 8) * 16 + kt * 8 + tig];
            qf[s][kt][2] = smw[base + (qbase + gid) * 16 + kt * 8 + tig + 4];
            qf[s][kt][3] = smw[base + (qbase + gid + 8) * 16 + kt * 8 + tig + 4];
        }

    float acc[4][4];
#pragma unroll
    for (int i = 0; i < 4; i++)
#pragma unroll
        for (int j = 0; j < 4; j++) acc[i][j] = 0.f;
    float l0 = 0.f, l8 = 0.f;

    for (int nc = 0; nc < 32; nc++) {
        const int db = nc & 1;
        const bool pre = (nc + 1 < 32);

        if (pre) {
            const int kcK = c0K + (nc + 1) * 64 * DD;
            const int kcV = c0V + (nc + 1) * 32;
#pragma unroll
            for (int it = 0; it < 2; it++) {
                kreg[it] = *(const uint4*)(k_src[it] + kcK + k_off[it]);
                vreg[it] = *(const uint4*)(v_src[it] + kcV + v_goff[it]);
            }
        }

        // ---- QK: ldmatrix x4 = {kh0,kh1,kl0,kl1} per (kt,nt) ----
        float c[8][4];
#pragma unroll
        for (int nt = 0; nt < 8; nt++)
#pragma unroll
            for (int j = 0; j < 4; j++) c[nt][j] = 0.f;

        const uint32_t qk_db = qk_lane + (uint32_t)(db * 2560) * 4;
#pragma unroll
        for (int kt = 0; kt < 2; kt++)
#pragma unroll
            for (int nt = 0; nt < 8; nt++) {
                uint32_t kh0, kh1, kl0, kl1;
                ldsm_x4(kh0, kh1, kl0, kl1,
                        qk_db + (uint32_t)(nt * 160 + kt * 8) * 4);
                mma_bf16(c[nt], qf[0][kt], kh0, kh1);
                mma_bf16(c[nt], qf[0][kt], kl0, kl1);
                mma_bf16(c[nt], qf[1][kt], kh0, kh1);
            }

        if (pre) {
            const int o2 = (db ^ 1) * 2560;
#pragma unroll
            for (int it = 0; it < 2; it++) {
                *(uint4*)&smw[KBASE_W + o2 + k_drel[it]] = kreg[it];
                *(uint4*)&smw[VBASE_W + o2 + v_drel[it]] = vreg[it];
            }
        }

        // ---- softmax: p = ex2(s), repack to A-frags ----
        uint32_t aph[4][4], apl[4][4];
#pragma unroll
        for (int nt = 0; nt < 8; nt++) {
            const float p0 = ex2f(c[nt][0]);
            const float p1 = ex2f(c[nt][1]);
            const float p2 = ex2f(c[nt][2]);
            const float p3 = ex2f(c[nt][3]);
            l0 += p0 + p1;
            l8 += p2 + p3;
            const uint32_t h01 = cvt_bf2(p0, p1);
            const uint32_t h23 = cvt_bf2(p2, p3);
            const float r0 = p0 - __uint_as_float(h01 << 16);
            const float r1 = p1 - __uint_as_float(h01 & 0xFFFF0000u);
            const float r2 = p2 - __uint_as_float(h23 << 16);
            const float r3 = p3 - __uint_as_float(h23 & 0xFFFF0000u);
            const uint32_t q01 = cvt_bf2(r0, r1);
            const uint32_t q23 = cvt_bf2(r2, r3);
            const int kt2 = nt >> 1, hi = (nt & 1) * 2;
            aph[kt2][hi]     = h01; aph[kt2][hi + 1] = h23;
            apl[kt2][hi]     = q01; apl[kt2][hi + 1] = q23;
        }

        // ---- PV: ldmatrix x4 = {vh0,vh1,vl0,vl1} per (kt2,nt2) ----
        const uint32_t pv_db = pv_lane + (uint32_t)(db * 2560) * 4;
#pragma unroll
        for (int kt2 = 0; kt2 < 4; kt2++)
#pragma unroll
            for (int nt2 = 0; nt2 < 4; nt2++) {
                uint32_t vh0, vh1, vl0, vl1;
                ldsm_x4(vh0, vh1, vl0, vl1,
                        pv_db + (uint32_t)(nt2 * 288 + kt2 * 8) * 4);
                mma_bf16(acc[nt2], aph[kt2], vh0, vh1);
                mma_bf16(acc[nt2], aph[kt2], vl0, vl1);
                mma_bf16(acc[nt2], apl[kt2], vh0, vh1);
            }

        __syncthreads();
    }

    // ---- epilogue: reduce l; write RAW partials ----
    l0 += __shfl_xor_sync(0xffffffffu, l0, 1, 4);
    l0 += __shfl_xor_sync(0xffffffffu, l0, 2, 4);
    l8 += __shfl_xor_sync(0xffffffffu, l8, 1, 4);
    l8 += __shfl_xor_sync(0xffffffffu, l8, 2, 4);

    const size_t row0 = (size_t)b * SS + q0 + qbase + gid;
    float* pa = g_pacc[half];
    if (tig == 0) {
        g_pl[half][row0]     = l0;
        g_pl[half][row0 + 8] = l8;
    }
#pragma unroll
    for (int nt2 = 0; nt2 < 4; nt2++) {
        *(float2*)(pa + row0 * DD + nt2 * 8 + tig * 2) =
            make_float2(acc[nt2][0], acc[nt2][1]);
        *(float2*)(pa + (row0 + 8) * DD + nt2 * 8 + tig * 2) =
            make_float2(acc[nt2][2], acc[nt2][3]);
    }
}

// ---------------------------------------------------------------------------
// Merge: out = (acc0 + acc1) * scaling / (l0 + l1).
// ---------------------------------------------------------------------------
__global__ __launch_bounds__(256, 1) void merge_kernel(float* __restrict__ out)
{
    const int i4 = blockIdx.x * 256 + threadIdx.x;
    const int row = i4 >> 3;
    const float l = g_pl[0][row] + g_pl[1][row];
    const float s = 0.17677669529663687f / l;
    const float4 a = ((const float4*)g_pacc[0])[i4];
    const float4 b = ((const float4*)g_pacc[1])[i4];
    float4 o;
    o.x = (a.x + b.x) * s; o.y = (a.y + b.y) * s;
    o.z = (a.z + b.z) * s; o.w = (a.w + b.w) * s;
    ((float4*)out)[i4] = o;
}

// ---------------------------------------------------------------------------
extern "C" void kernel_launch(void* const* d_in, const int* in_sizes, int n_in,
                              void* d_out, int out_size)
{
    const float* x  = (const float*)d_in[0];
    const float* Wq = (const float*)d_in[1];
    const float* Wk = (const float*)d_in[2];
    const float* Wv = (const float*)d_in[3];
    float* out = (float*)d_out;

    cudaFuncSetAttribute(proj_mma, cudaFuncAttributeMaxDynamicSharedMemorySize, PROJ_SMEM_BYTES);
    proj_mma<<<(BB * SS) / 64, 256, PROJ_SMEM_BYTES>>>(x, Wq, Wk, Wv);

    cudaFuncSetAttribute(attn_mma, cudaFuncAttributeMaxDynamicSharedMemorySize, SMEM_BYTES);
    dim3 grid(SS / 128, BB, 2);
    attn_mma<<<grid, 256, SMEM_BYTES>>>();

    merge_kernel<<<(BB * SS * DD / 4) / 256, 256>>>(out);
}